// round 4
// baseline (speedup 1.0000x reference)
#include <cuda_runtime.h>
#include <cuda_fp16.h>
#include <math.h>
#include <mma.h>

using namespace nvcuda;

// ---------------------------------------------------------------------------
// GCN2: fc1 -> 3x(GCN2Conv + BN + ReLU) -> fc2, 50k nodes / 800k edges.
// R3: fp16 gather buffers (xs, x0) halve SpMM L2 traffic; dead g_xcur / fc1
// fp32 output writes removed; fc1 uses 3xTF32 error compensation (error model:
// fc1 tf32 rounding dominated rel_err).
// ---------------------------------------------------------------------------

#define N_NODES 50000
#define E_EDGES 800000
#define IN_DIM  256
#define H_DIM   96
#define OUT_DIM 40
#define SCAN_NB_MAX 256

// ---- scratch ---------------------------------------------------------------
__device__ float g_dinv[N_NODES];
__device__ int   g_cnt[N_NODES];
__device__ int   g_fill[N_NODES];
__device__ int   g_start[N_NODES + 1];
__device__ int   g_bsum[SCAN_NB_MAX];
__device__ int   g_boff[SCAN_NB_MAX];
__device__ int   g_src[E_EDGES];
__device__ __align__(16) __half g_x0h[N_NODES * H_DIM];  // fc1 out (residual), fp16
__device__ __align__(16) __half g_xsh[N_NODES * H_DIM];  // dinv-prescaled feats, fp16
__device__ __align__(16) float  g_hp[N_NODES * H_DIM];   // post-aggregation (fp32)
__device__ __align__(16) float  g_h2[N_NODES * H_DIM];   // post identity-mapping
__device__ float g_sum[3 * H_DIM];
__device__ float g_sumsq[3 * H_DIM];
__device__ int   g_is64;

// ---------------------------------------------------------------------------
// 0) dtype detection: int64 edge_index has zero high words at odd i32 slots
// ---------------------------------------------------------------------------
__global__ void detect_idx_kernel(const int* __restrict__ idx, int n_i32) {
    __shared__ int nz;
    if (threadIdx.x == 0) nz = 0;
    __syncthreads();
    int found = 0;
    for (int it = 0; it < 8; it++) {
        int p = 2 * (int)threadIdx.x + 1 + it * 1024;
        if (p < n_i32 && idx[p] != 0) found = 1;
    }
    if (found) atomicOr(&nz, 1);
    __syncthreads();
    if (threadIdx.x == 0) g_is64 = (nz == 0) ? 1 : 0;
}

__device__ __forceinline__ int load_row(const int* idx, int e) {
    return g_is64 ? idx[2 * e] : idx[e];
}
__device__ __forceinline__ int load_col(const int* idx, int e, int E) {
    return g_is64 ? idx[2 * (E + e)] : idx[E + e];
}

// ---------------------------------------------------------------------------
// 1) CSR build
// ---------------------------------------------------------------------------
__global__ void zero_all_kernel(int N) {
    int i = blockIdx.x * blockDim.x + threadIdx.x;
    if (i < N) { g_cnt[i] = 0; g_fill[i] = 0; }
    if (i < 3 * H_DIM) { g_sum[i] = 0.f; g_sumsq[i] = 0.f; }
}

__global__ void count_edges_kernel(const int* __restrict__ idx, int E) {
    int e = blockIdx.x * blockDim.x + threadIdx.x;
    if (e < E) atomicAdd(&g_cnt[load_col(idx, e, E)], 1);
}

__global__ void scan1_kernel(int N) {
    __shared__ int sm[256];
    int t = threadIdx.x;
    int i = blockIdx.x * 256 + t;
    int c = (i < N) ? g_cnt[i] : 0;
    if (i < N) g_dinv[i] = rsqrtf((float)(c + 1));
    sm[t] = c;
    __syncthreads();
    int acc = c;
#pragma unroll
    for (int off = 1; off < 256; off <<= 1) {
        int v = (t >= off) ? sm[t - off] : 0;
        __syncthreads();
        acc += v;
        sm[t] = acc;
        __syncthreads();
    }
    if (i < N) g_start[i] = acc - c;
    if (t == 255) g_bsum[blockIdx.x] = acc;
}

__global__ void scan2_kernel(int NB, int N) {
    __shared__ int sm[SCAN_NB_MAX];
    int t = threadIdx.x;
    int v = (t < NB) ? g_bsum[t] : 0;
    sm[t] = v;
    __syncthreads();
    int acc = v;
#pragma unroll
    for (int off = 1; off < SCAN_NB_MAX; off <<= 1) {
        int u = (t >= off) ? sm[t - off] : 0;
        __syncthreads();
        acc += u;
        sm[t] = acc;
        __syncthreads();
    }
    if (t < NB) g_boff[t] = acc - v;
    if (t == NB - 1) g_start[N] = acc;
}

__global__ void scan3_kernel(int N) {
    int i = blockIdx.x * 256 + threadIdx.x;
    if (i < N) g_start[i] += g_boff[blockIdx.x];
}

__global__ void scatter_edges_kernel(const int* __restrict__ idx, int E) {
    int e = blockIdx.x * blockDim.x + threadIdx.x;
    if (e < E) {
        int r = load_row(idx, e);
        int c = load_col(idx, e, E);
        int p = g_start[c] + atomicAdd(&g_fill[c], 1);
        g_src[p] = r;
    }
}

// ---------------------------------------------------------------------------
// 2) TF32 tensor-core GEMM, N fixed = 96.  C = A[M,K] @ B[K,96]
//    BM=64 BN=96 BK=16, 256 threads (8 warps 4x2).  x3 = 3xTF32 compensation.
//    Epilogues: bias/relu + half x0/xs write (fc1), blend + stats (conv).
// ---------------------------------------------------------------------------
#define GBM 64
#define GBK 16
#define ALD 20
#define BLD 100

__global__ void __launch_bounds__(256) gemm_tf32_kernel(
    const float* __restrict__ A, const float* __restrict__ B,
    const float* __restrict__ bias, const float* __restrict__ blend,
    float ba, float bb, int do_relu, int write_half, int stat_layer, int x3,
    float* __restrict__ out, int M, int K)
{
    __shared__ union SmU {
        struct {
            float As[GBM][ALD]; float Al[GBM][ALD];
            float Bs[GBK][BLD]; float Bl[GBK][BLD];
        } ld;
        float Csm[GBM][BLD];
    } sm;
    __shared__ float RedS[8][96];
    __shared__ float RedQ[8][96];

    int tid = threadIdx.x;
    int w = tid >> 5;
    int wm = w >> 1;
    int wn = w & 1;
    int bm = blockIdx.x * GBM;

    wmma::fragment<wmma::accumulator, 16, 16, 8, float> c[3];
#pragma unroll
    for (int t = 0; t < 3; t++) wmma::fill_fragment(c[t], 0.f);

    int arow = tid >> 2;
    int aq   = (tid & 3) * 4;

    for (int k0 = 0; k0 < K; k0 += GBK) {
        float4 av = make_float4(0.f, 0.f, 0.f, 0.f);
        int gr = bm + arow;
        if (gr < M) av = *(const float4*)(A + (size_t)gr * K + k0 + aq);
        float h0 = wmma::__float_to_tf32(av.x);
        float h1 = wmma::__float_to_tf32(av.y);
        float h2v = wmma::__float_to_tf32(av.z);
        float h3 = wmma::__float_to_tf32(av.w);
        sm.ld.As[arow][aq + 0] = h0;
        sm.ld.As[arow][aq + 1] = h1;
        sm.ld.As[arow][aq + 2] = h2v;
        sm.ld.As[arow][aq + 3] = h3;
        if (x3) {
            sm.ld.Al[arow][aq + 0] = wmma::__float_to_tf32(av.x - h0);
            sm.ld.Al[arow][aq + 1] = wmma::__float_to_tf32(av.y - h1);
            sm.ld.Al[arow][aq + 2] = wmma::__float_to_tf32(av.z - h2v);
            sm.ld.Al[arow][aq + 3] = wmma::__float_to_tf32(av.w - h3);
        }
#pragma unroll
        for (int j = 0; j < 6; j++) {
            int i = tid + j * 256;
            int bk = i / 96, bn = i - bk * 96;
            float bv = B[(size_t)(k0 + bk) * 96 + bn];
            float bh = wmma::__float_to_tf32(bv);
            sm.ld.Bs[bk][bn] = bh;
            if (x3) sm.ld.Bl[bk][bn] = wmma::__float_to_tf32(bv - bh);
        }
        __syncthreads();
#pragma unroll
        for (int kk = 0; kk < 2; kk++) {
            wmma::fragment<wmma::matrix_a, 16, 16, 8, wmma::precision::tf32, wmma::row_major> ah, al;
            wmma::load_matrix_sync(ah, &sm.ld.As[wm * 16][kk * 8], ALD);
            if (x3) wmma::load_matrix_sync(al, &sm.ld.Al[wm * 16][kk * 8], ALD);
#pragma unroll
            for (int t = 0; t < 3; t++) {
                wmma::fragment<wmma::matrix_b, 16, 16, 8, wmma::precision::tf32, wmma::row_major> bh, bl;
                wmma::load_matrix_sync(bh, &sm.ld.Bs[kk * 8][wn * 48 + t * 16], BLD);
                wmma::mma_sync(c[t], ah, bh, c[t]);
                if (x3) {
                    wmma::load_matrix_sync(bl, &sm.ld.Bl[kk * 8][wn * 48 + t * 16], BLD);
                    wmma::mma_sync(c[t], al, bh, c[t]);
                    wmma::mma_sync(c[t], ah, bl, c[t]);
                }
            }
        }
        __syncthreads();
    }

#pragma unroll
    for (int t = 0; t < 3; t++)
        wmma::store_matrix_sync(&sm.Csm[wm * 16][wn * 48 + t * 16], c[t], BLD,
                                wmma::mem_row_major);
    __syncthreads();

    int tx = tid & 31, ty = tid >> 5;
    float s_c[3] = {0.f, 0.f, 0.f};
    float q_c[3] = {0.f, 0.f, 0.f};
#pragma unroll
    for (int rr = 0; rr < 8; rr++) {
        int row = bm + ty * 8 + rr;
        if (row >= M) continue;
        float dv = write_half ? g_dinv[row] : 0.f;
#pragma unroll
        for (int j = 0; j < 3; j++) {
            int col = tx + j * 32;
            float v = sm.Csm[ty * 8 + rr][col];
            if (bias)  v += bias[col];
            if (blend) v = ba * blend[(size_t)row * 96 + col] + bb * v;
            if (do_relu) v = fmaxf(v, 0.f);
            size_t o = (size_t)row * 96 + col;
            if (out) out[o] = v;
            if (write_half) {
                g_x0h[o] = __float2half(v);
                g_xsh[o] = __float2half(dv * v);
            }
            if (stat_layer >= 0) { s_c[j] += v; q_c[j] += v * v; }
        }
    }

    if (stat_layer >= 0) {
#pragma unroll
        for (int j = 0; j < 3; j++) {
            RedS[ty][tx + j * 32] = s_c[j];
            RedQ[ty][tx + j * 32] = q_c[j];
        }
        __syncthreads();
        if (ty == 0) {
#pragma unroll
            for (int j = 0; j < 3; j++) {
                int col = tx + j * 32;
                float s = 0.f, q = 0.f;
#pragma unroll
                for (int y = 0; y < 8; y++) { s += RedS[y][col]; q += RedQ[y][col]; }
                atomicAdd(&g_sum[stat_layer * H_DIM + col], s);
                atomicAdd(&g_sumsq[stat_layer * H_DIM + col], q);
            }
        }
    }
}

// ---------------------------------------------------------------------------
// 3) gather SpMM over fp16 features: one warp per destination node.
//    Lanes 0..23 each own 4 consecutive features (uint2 = 4 halves / load).
//    hp[c] = 0.9 * dinv[c] * (xs[c] + sum_src xs[src]) + 0.1 * x0[c]
// ---------------------------------------------------------------------------
__device__ __forceinline__ float4 h4_to_f4(uint2 r) {
    __half2 a = *reinterpret_cast<__half2*>(&r.x);
    __half2 b = *reinterpret_cast<__half2*>(&r.y);
    float2 fa = __half22float2(a), fb = __half22float2(b);
    return make_float4(fa.x, fa.y, fb.x, fb.y);
}

__global__ void __launch_bounds__(256) gather_kernel(
    const __half* __restrict__ xs, const __half* __restrict__ x0,
    float* __restrict__ hp, int N)
{
    int warp = (blockIdx.x * blockDim.x + threadIdx.x) >> 5;
    int lane = threadIdx.x & 31;
    if (warp >= N) return;
    int c = warp;
    int s0 = g_start[c], s1 = g_start[c + 1];
    bool act = lane < 24;
    size_t base = (size_t)c * 96 + 4 * lane;
    float4 a = make_float4(0.f, 0.f, 0.f, 0.f);
    if (act) a = h4_to_f4(*(const uint2*)(xs + base));   // self loop term
    int j = s0;
    for (; j + 1 < s1; j += 2) {
        int sA = g_src[j], sB = g_src[j + 1];
        if (act) {
            float4 vA = h4_to_f4(*(const uint2*)(xs + (size_t)sA * 96 + 4 * lane));
            float4 vB = h4_to_f4(*(const uint2*)(xs + (size_t)sB * 96 + 4 * lane));
            a.x += vA.x + vB.x; a.y += vA.y + vB.y;
            a.z += vA.z + vB.z; a.w += vA.w + vB.w;
        }
    }
    if (j < s1) {
        int sA = g_src[j];
        if (act) {
            float4 vA = h4_to_f4(*(const uint2*)(xs + (size_t)sA * 96 + 4 * lane));
            a.x += vA.x; a.y += vA.y; a.z += vA.z; a.w += vA.w;
        }
    }
    if (act) {
        float wgt = 0.9f * g_dinv[c];
        float4 x0v = h4_to_f4(*(const uint2*)(x0 + base));
        float4 o;
        o.x = wgt * a.x + 0.1f * x0v.x;
        o.y = wgt * a.y + 0.1f * x0v.y;
        o.z = wgt * a.z + 0.1f * x0v.z;
        o.w = wgt * a.w + 0.1f * x0v.w;
        *(float4*)(hp + base) = o;
    }
}

// ---------------------------------------------------------------------------
// 4) BN apply + relu -> write next-layer fp16 xs only (g_xcur was dead)
// ---------------------------------------------------------------------------
__global__ void __launch_bounds__(256) bn_apply_kernel(
    const float* __restrict__ h2, const float* __restrict__ gamma,
    const float* __restrict__ beta, int layer, int N)
{
    __shared__ float sc[96], sh[96];
    if (threadIdx.x < 96) {
        int h = threadIdx.x;
        float m  = g_sum[layer * H_DIM + h] / (float)N;
        float vr = g_sumsq[layer * H_DIM + h] / (float)N - m * m;
        float rs = rsqrtf(vr + 1e-5f);
        float s = gamma[h] * rs;
        sc[h] = s;
        sh[h] = beta[h] - m * s;
    }
    __syncthreads();
    int i = blockIdx.x * blockDim.x + threadIdx.x;
    int total = N * 96;
    if (i < total) {
        int h = i % 96;
        int r = i / 96;
        float v = fmaxf(sc[h] * h2[i] + sh[h], 0.f);
        g_xsh[i] = __float2half(g_dinv[r] * v);
    }
}

// ---------------------------------------------------------------------------
// 5) fc2: out[M,40] = relu(BN(A))[M,96] @ W[96,40] + b   (layer-2 BN fused)
// ---------------------------------------------------------------------------
__global__ void __launch_bounds__(320) fc2_kernel(
    const float* __restrict__ A, const float* __restrict__ W,
    const float* __restrict__ bias, const float* __restrict__ gamma,
    const float* __restrict__ beta, int layer, float* __restrict__ out, int M)
{
    __shared__ float Ws[96 * 40];
    __shared__ float bs[40];
    __shared__ float Asm[8][96];
    __shared__ float sc[96], sh[96];
    int tid = threadIdx.x;
    for (int i = tid; i < 96 * 40; i += 320) Ws[i] = W[i];
    if (tid < 40) bs[tid] = bias[tid];
    if (tid < 96) {
        int h = tid;
        float m  = g_sum[layer * H_DIM + h] / (float)M;
        float vr = g_sumsq[layer * H_DIM + h] / (float)M - m * m;
        float rs = rsqrtf(vr + 1e-5f);
        float s = gamma[h] * rs;
        sc[h] = s;
        sh[h] = beta[h] - m * s;
    }
    int tx = tid % 40, ty = tid / 40;
    for (int r0 = blockIdx.x * 8; r0 < M; r0 += gridDim.x * 8) {
        __syncthreads();
        for (int i = tid; i < 768; i += 320) {
            int r = i / 96, k = i - r * 96;
            float v = (r0 + r < M) ? A[(size_t)(r0 + r) * 96 + k] : 0.f;
            Asm[r][k] = fmaxf(sc[k] * v + sh[k], 0.f);
        }
        __syncthreads();
        float acc = bs[tx];
#pragma unroll
        for (int k = 0; k < 96; k++) acc += Asm[ty][k] * Ws[k * 40 + tx];
        if (r0 + ty < M) out[(size_t)(r0 + ty) * 40 + tx] = acc;
    }
}

// ---------------------------------------------------------------------------
// launch
// ---------------------------------------------------------------------------
extern "C" void kernel_launch(void* const* d_in, const int* in_sizes, int n_in,
                              void* d_out, int out_size) {
    const float* x_in    = (const float*)d_in[0];
    const int*   eidx    = (const int*)d_in[1];
    const float* fc1_w   = (const float*)d_in[2];
    const float* fc1_b   = (const float*)d_in[3];
    const float* conv_w  = (const float*)d_in[4];
    const float* bn_g    = (const float*)d_in[5];
    const float* bn_b    = (const float*)d_in[6];
    const float* fc2_w   = (const float*)d_in[7];
    const float* fc2_b   = (const float*)d_in[8];
    float* out = (float*)d_out;

    int N = in_sizes[0] / IN_DIM;
    int E = in_sizes[1] / 2;
    if (N > N_NODES) N = N_NODES;
    if (E > E_EDGES) E = E_EDGES;
    int NB = (N + 255) / 256;

    __half *p_xsh, *p_x0h;
    float *p_hp, *p_h2;
    cudaGetSymbolAddress((void**)&p_xsh, g_xsh);
    cudaGetSymbolAddress((void**)&p_x0h, g_x0h);
    cudaGetSymbolAddress((void**)&p_hp, g_hp);
    cudaGetSymbolAddress((void**)&p_h2, g_h2);

    // ---- graph preprocessing (CSR + dinv) ----
    detect_idx_kernel<<<1, 512>>>(eidx, 2 * E);
    zero_all_kernel<<<NB, 256>>>(N);
    count_edges_kernel<<<(E + 255) / 256, 256>>>(eidx, E);
    scan1_kernel<<<NB, 256>>>(N);
    scan2_kernel<<<1, SCAN_NB_MAX>>>(NB, N);
    scan3_kernel<<<NB, 256>>>(N);
    scatter_edges_kernel<<<(E + 255) / 256, 256>>>(eidx, E);

    int gemm_grid = (N + GBM - 1) / GBM;

    // ---- fc1 + relu: 3xTF32, writes only fp16 x0h + xsh ----
    gemm_tf32_kernel<<<gemm_grid, 256>>>(
        x_in, fc1_w, fc1_b, nullptr, 0.f, 0.f, /*relu=*/1, /*write_half=*/1,
        /*stat_layer=*/-1, /*x3=*/1, /*out=*/nullptr, N, IN_DIM);

    int gather_grid = (N * 32 + 255) / 256;
    int ew_grid = (N * 96 + 255) / 256;

    for (int i = 0; i < 3; i++) {
        float beta = logf(0.5f / (float)(i + 1) + 1.0f);
        gather_kernel<<<gather_grid, 256>>>(p_xsh, p_x0h, p_hp, N);
        gemm_tf32_kernel<<<gemm_grid, 256>>>(
            p_hp, conv_w + (size_t)i * H_DIM * H_DIM, nullptr, p_hp,
            1.f - beta, beta, /*relu=*/0, /*write_half=*/0, /*stat_layer=*/i,
            /*x3=*/0, p_h2, N, H_DIM);
        if (i < 2) {
            bn_apply_kernel<<<ew_grid, 256>>>(
                p_h2, bn_g + i * H_DIM, bn_b + i * H_DIM, i, N);
        }
    }

    // ---- fc2 with layer-2 BN+ReLU fused ----
    fc2_kernel<<<512, 320>>>(p_h2, fc2_w, fc2_b, bn_g + 2 * H_DIM,
                             bn_b + 2 * H_DIM, 2, out, N);
}

// round 5
// speedup vs baseline: 1.4006x; 1.4006x over previous
#include <cuda_runtime.h>
#include <cuda_fp16.h>
#include <math.h>
#include <mma.h>

using namespace nvcuda;

// ---------------------------------------------------------------------------
// GCN2: fc1 -> 3x(GCN2Conv + BN + ReLU) -> fc2, 50k nodes / 800k edges.
// R5: revert 3xTF32 comp (zero error benefit, ~160us cost), keep fp16 gather
// buffers, unroll gather x4 for MLP (gather is L2-latency-bound, not BW-bound).
// ---------------------------------------------------------------------------

#define N_NODES 50000
#define E_EDGES 800000
#define IN_DIM  256
#define H_DIM   96
#define OUT_DIM 40
#define SCAN_NB_MAX 256

// ---- scratch ---------------------------------------------------------------
__device__ float g_dinv[N_NODES];
__device__ int   g_cnt[N_NODES];
__device__ int   g_fill[N_NODES];
__device__ int   g_start[N_NODES + 1];
__device__ int   g_bsum[SCAN_NB_MAX];
__device__ int   g_boff[SCAN_NB_MAX];
__device__ int   g_src[E_EDGES];
__device__ __align__(16) __half g_x0h[N_NODES * H_DIM];  // fc1 out (residual), fp16
__device__ __align__(16) __half g_xsh[N_NODES * H_DIM];  // dinv-prescaled feats, fp16
__device__ __align__(16) float  g_hp[N_NODES * H_DIM];   // post-aggregation (fp32)
__device__ __align__(16) float  g_h2[N_NODES * H_DIM];   // post identity-mapping
__device__ float g_sum[3 * H_DIM];
__device__ float g_sumsq[3 * H_DIM];
__device__ int   g_is64;

// ---------------------------------------------------------------------------
// 0) dtype detection: int64 edge_index has zero high words at odd i32 slots
// ---------------------------------------------------------------------------
__global__ void detect_idx_kernel(const int* __restrict__ idx, int n_i32) {
    __shared__ int nz;
    if (threadIdx.x == 0) nz = 0;
    __syncthreads();
    int found = 0;
    for (int it = 0; it < 8; it++) {
        int p = 2 * (int)threadIdx.x + 1 + it * 1024;
        if (p < n_i32 && idx[p] != 0) found = 1;
    }
    if (found) atomicOr(&nz, 1);
    __syncthreads();
    if (threadIdx.x == 0) g_is64 = (nz == 0) ? 1 : 0;
}

__device__ __forceinline__ int load_row(const int* idx, int e) {
    return g_is64 ? idx[2 * e] : idx[e];
}
__device__ __forceinline__ int load_col(const int* idx, int e, int E) {
    return g_is64 ? idx[2 * (E + e)] : idx[E + e];
}

// ---------------------------------------------------------------------------
// 1) CSR build
// ---------------------------------------------------------------------------
__global__ void zero_all_kernel(int N) {
    int i = blockIdx.x * blockDim.x + threadIdx.x;
    if (i < N) { g_cnt[i] = 0; g_fill[i] = 0; }
    if (i < 3 * H_DIM) { g_sum[i] = 0.f; g_sumsq[i] = 0.f; }
}

__global__ void count_edges_kernel(const int* __restrict__ idx, int E) {
    int e = blockIdx.x * blockDim.x + threadIdx.x;
    if (e < E) atomicAdd(&g_cnt[load_col(idx, e, E)], 1);
}

__global__ void scan1_kernel(int N) {
    __shared__ int sm[256];
    int t = threadIdx.x;
    int i = blockIdx.x * 256 + t;
    int c = (i < N) ? g_cnt[i] : 0;
    if (i < N) g_dinv[i] = rsqrtf((float)(c + 1));
    sm[t] = c;
    __syncthreads();
    int acc = c;
#pragma unroll
    for (int off = 1; off < 256; off <<= 1) {
        int v = (t >= off) ? sm[t - off] : 0;
        __syncthreads();
        acc += v;
        sm[t] = acc;
        __syncthreads();
    }
    if (i < N) g_start[i] = acc - c;
    if (t == 255) g_bsum[blockIdx.x] = acc;
}

__global__ void scan2_kernel(int NB, int N) {
    __shared__ int sm[SCAN_NB_MAX];
    int t = threadIdx.x;
    int v = (t < NB) ? g_bsum[t] : 0;
    sm[t] = v;
    __syncthreads();
    int acc = v;
#pragma unroll
    for (int off = 1; off < SCAN_NB_MAX; off <<= 1) {
        int u = (t >= off) ? sm[t - off] : 0;
        __syncthreads();
        acc += u;
        sm[t] = acc;
        __syncthreads();
    }
    if (t < NB) g_boff[t] = acc - v;
    if (t == NB - 1) g_start[N] = acc;
}

__global__ void scan3_kernel(int N) {
    int i = blockIdx.x * 256 + threadIdx.x;
    if (i < N) g_start[i] += g_boff[blockIdx.x];
}

__global__ void scatter_edges_kernel(const int* __restrict__ idx, int E) {
    int e = blockIdx.x * blockDim.x + threadIdx.x;
    if (e < E) {
        int r = load_row(idx, e);
        int c = load_col(idx, e, E);
        int p = g_start[c] + atomicAdd(&g_fill[c], 1);
        g_src[p] = r;
    }
}

// ---------------------------------------------------------------------------
// 2) TF32 tensor-core GEMM, N fixed = 96.  C = A[M,K] @ B[K,96]
//    BM=64 BN=96 BK=16, 256 threads (8 warps 4x2).
//    Epilogues: bias/relu + half x0/xs write (fc1), blend + stats (conv).
// ---------------------------------------------------------------------------
#define GBM 64
#define GBK 16
#define ALD 20
#define BLD 100

__global__ void __launch_bounds__(256) gemm_tf32_kernel(
    const float* __restrict__ A, const float* __restrict__ B,
    const float* __restrict__ bias, const float* __restrict__ blend,
    float ba, float bb, int do_relu, int write_half, int stat_layer,
    float* __restrict__ out, int M, int K)
{
    __shared__ union SmU {
        struct { float As[GBM][ALD]; float Bs[GBK][BLD]; } ld;
        float Csm[GBM][BLD];
    } sm;
    __shared__ float RedS[8][96];
    __shared__ float RedQ[8][96];

    int tid = threadIdx.x;
    int w = tid >> 5;
    int wm = w >> 1;
    int wn = w & 1;
    int bm = blockIdx.x * GBM;

    wmma::fragment<wmma::accumulator, 16, 16, 8, float> c[3];
#pragma unroll
    for (int t = 0; t < 3; t++) wmma::fill_fragment(c[t], 0.f);

    int arow = tid >> 2;
    int aq   = (tid & 3) * 4;

    for (int k0 = 0; k0 < K; k0 += GBK) {
        float4 av = make_float4(0.f, 0.f, 0.f, 0.f);
        int gr = bm + arow;
        if (gr < M) av = *(const float4*)(A + (size_t)gr * K + k0 + aq);
        sm.ld.As[arow][aq + 0] = wmma::__float_to_tf32(av.x);
        sm.ld.As[arow][aq + 1] = wmma::__float_to_tf32(av.y);
        sm.ld.As[arow][aq + 2] = wmma::__float_to_tf32(av.z);
        sm.ld.As[arow][aq + 3] = wmma::__float_to_tf32(av.w);
#pragma unroll
        for (int j = 0; j < 6; j++) {
            int i = tid + j * 256;
            int bk = i / 96, bn = i - bk * 96;
            sm.ld.Bs[bk][bn] = wmma::__float_to_tf32(B[(size_t)(k0 + bk) * 96 + bn]);
        }
        __syncthreads();
#pragma unroll
        for (int kk = 0; kk < 2; kk++) {
            wmma::fragment<wmma::matrix_a, 16, 16, 8, wmma::precision::tf32, wmma::row_major> a;
            wmma::load_matrix_sync(a, &sm.ld.As[wm * 16][kk * 8], ALD);
#pragma unroll
            for (int t = 0; t < 3; t++) {
                wmma::fragment<wmma::matrix_b, 16, 16, 8, wmma::precision::tf32, wmma::row_major> b;
                wmma::load_matrix_sync(b, &sm.ld.Bs[kk * 8][wn * 48 + t * 16], BLD);
                wmma::mma_sync(c[t], a, b, c[t]);
            }
        }
        __syncthreads();
    }

#pragma unroll
    for (int t = 0; t < 3; t++)
        wmma::store_matrix_sync(&sm.Csm[wm * 16][wn * 48 + t * 16], c[t], BLD,
                                wmma::mem_row_major);
    __syncthreads();

    int tx = tid & 31, ty = tid >> 5;
    float s_c[3] = {0.f, 0.f, 0.f};
    float q_c[3] = {0.f, 0.f, 0.f};
#pragma unroll
    for (int rr = 0; rr < 8; rr++) {
        int row = bm + ty * 8 + rr;
        if (row >= M) continue;
        float dv = write_half ? g_dinv[row] : 0.f;
#pragma unroll
        for (int j = 0; j < 3; j++) {
            int col = tx + j * 32;
            float v = sm.Csm[ty * 8 + rr][col];
            if (bias)  v += bias[col];
            if (blend) v = ba * blend[(size_t)row * 96 + col] + bb * v;
            if (do_relu) v = fmaxf(v, 0.f);
            size_t o = (size_t)row * 96 + col;
            if (out) out[o] = v;
            if (write_half) {
                g_x0h[o] = __float2half(v);
                g_xsh[o] = __float2half(dv * v);
            }
            if (stat_layer >= 0) { s_c[j] += v; q_c[j] += v * v; }
        }
    }

    if (stat_layer >= 0) {
#pragma unroll
        for (int j = 0; j < 3; j++) {
            RedS[ty][tx + j * 32] = s_c[j];
            RedQ[ty][tx + j * 32] = q_c[j];
        }
        __syncthreads();
        if (ty == 0) {
#pragma unroll
            for (int j = 0; j < 3; j++) {
                int col = tx + j * 32;
                float s = 0.f, q = 0.f;
#pragma unroll
                for (int y = 0; y < 8; y++) { s += RedS[y][col]; q += RedQ[y][col]; }
                atomicAdd(&g_sum[stat_layer * H_DIM + col], s);
                atomicAdd(&g_sumsq[stat_layer * H_DIM + col], q);
            }
        }
    }
}

// ---------------------------------------------------------------------------
// 3) gather SpMM over fp16 features: one warp per destination node.
//    Lanes 0..23 own 4 consecutive features (uint2 = 4 halves / load).
//    Unroll x4 with batched index loads to maximize outstanding L2 reads.
//    hp[c] = 0.9 * dinv[c] * (xs[c] + sum_src xs[src]) + 0.1 * x0[c]
// ---------------------------------------------------------------------------
__device__ __forceinline__ float4 h4_to_f4(uint2 r) {
    __half2 a = *reinterpret_cast<__half2*>(&r.x);
    __half2 b = *reinterpret_cast<__half2*>(&r.y);
    float2 fa = __half22float2(a), fb = __half22float2(b);
    return make_float4(fa.x, fa.y, fb.x, fb.y);
}

__global__ void __launch_bounds__(256) gather_kernel(
    const __half* __restrict__ xs, const __half* __restrict__ x0,
    float* __restrict__ hp, int N)
{
    int warp = (blockIdx.x * blockDim.x + threadIdx.x) >> 5;
    int lane = threadIdx.x & 31;
    if (warp >= N) return;
    int c = warp;
    int s0 = g_start[c], s1 = g_start[c + 1];
    bool act = lane < 24;
    size_t base = (size_t)c * 96 + 4 * lane;
    float4 a = make_float4(0.f, 0.f, 0.f, 0.f);
    if (act) a = h4_to_f4(*(const uint2*)(xs + base));   // self-loop term
    int j = s0;
    for (; j + 3 < s1; j += 4) {
        int sA = g_src[j], sB = g_src[j + 1], sC = g_src[j + 2], sD = g_src[j + 3];
        if (act) {
            // issue all four row loads before any conversion (MLP=4)
            uint2 rA = *(const uint2*)(xs + (size_t)sA * 96 + 4 * lane);
            uint2 rB = *(const uint2*)(xs + (size_t)sB * 96 + 4 * lane);
            uint2 rC = *(const uint2*)(xs + (size_t)sC * 96 + 4 * lane);
            uint2 rD = *(const uint2*)(xs + (size_t)sD * 96 + 4 * lane);
            float4 vA = h4_to_f4(rA), vB = h4_to_f4(rB);
            float4 vC = h4_to_f4(rC), vD = h4_to_f4(rD);
            a.x += (vA.x + vB.x) + (vC.x + vD.x);
            a.y += (vA.y + vB.y) + (vC.y + vD.y);
            a.z += (vA.z + vB.z) + (vC.z + vD.z);
            a.w += (vA.w + vB.w) + (vC.w + vD.w);
        }
    }
    for (; j < s1; j++) {
        int sA = g_src[j];
        if (act) {
            float4 vA = h4_to_f4(*(const uint2*)(xs + (size_t)sA * 96 + 4 * lane));
            a.x += vA.x; a.y += vA.y; a.z += vA.z; a.w += vA.w;
        }
    }
    if (act) {
        float wgt = 0.9f * g_dinv[c];
        float4 x0v = h4_to_f4(*(const uint2*)(x0 + base));
        float4 o;
        o.x = wgt * a.x + 0.1f * x0v.x;
        o.y = wgt * a.y + 0.1f * x0v.y;
        o.z = wgt * a.z + 0.1f * x0v.z;
        o.w = wgt * a.w + 0.1f * x0v.w;
        *(float4*)(hp + base) = o;
    }
}

// ---------------------------------------------------------------------------
// 4) BN apply + relu -> write next-layer fp16 xs only
// ---------------------------------------------------------------------------
__global__ void __launch_bounds__(256) bn_apply_kernel(
    const float* __restrict__ h2, const float* __restrict__ gamma,
    const float* __restrict__ beta, int layer, int N)
{
    __shared__ float sc[96], sh[96];
    if (threadIdx.x < 96) {
        int h = threadIdx.x;
        float m  = g_sum[layer * H_DIM + h] / (float)N;
        float vr = g_sumsq[layer * H_DIM + h] / (float)N - m * m;
        float rs = rsqrtf(vr + 1e-5f);
        float s = gamma[h] * rs;
        sc[h] = s;
        sh[h] = beta[h] - m * s;
    }
    __syncthreads();
    int i = blockIdx.x * blockDim.x + threadIdx.x;
    int total = N * 96;
    if (i < total) {
        int h = i % 96;
        int r = i / 96;
        float v = fmaxf(sc[h] * h2[i] + sh[h], 0.f);
        g_xsh[i] = __float2half(g_dinv[r] * v);
    }
}

// ---------------------------------------------------------------------------
// 5) fc2: out[M,40] = relu(BN(A))[M,96] @ W[96,40] + b   (layer-2 BN fused)
// ---------------------------------------------------------------------------
__global__ void __launch_bounds__(320) fc2_kernel(
    const float* __restrict__ A, const float* __restrict__ W,
    const float* __restrict__ bias, const float* __restrict__ gamma,
    const float* __restrict__ beta, int layer, float* __restrict__ out, int M)
{
    __shared__ float Ws[96 * 40];
    __shared__ float bs[40];
    __shared__ float Asm[8][96];
    __shared__ float sc[96], sh[96];
    int tid = threadIdx.x;
    for (int i = tid; i < 96 * 40; i += 320) Ws[i] = W[i];
    if (tid < 40) bs[tid] = bias[tid];
    if (tid < 96) {
        int h = tid;
        float m  = g_sum[layer * H_DIM + h] / (float)M;
        float vr = g_sumsq[layer * H_DIM + h] / (float)M - m * m;
        float rs = rsqrtf(vr + 1e-5f);
        float s = gamma[h] * rs;
        sc[h] = s;
        sh[h] = beta[h] - m * s;
    }
    int tx = tid % 40, ty = tid / 40;
    for (int r0 = blockIdx.x * 8; r0 < M; r0 += gridDim.x * 8) {
        __syncthreads();
        for (int i = tid; i < 768; i += 320) {
            int r = i / 96, k = i - r * 96;
            float v = (r0 + r < M) ? A[(size_t)(r0 + r) * 96 + k] : 0.f;
            Asm[r][k] = fmaxf(sc[k] * v + sh[k], 0.f);
        }
        __syncthreads();
        float acc = bs[tx];
#pragma unroll
        for (int k = 0; k < 96; k++) acc += Asm[ty][k] * Ws[k * 40 + tx];
        if (r0 + ty < M) out[(size_t)(r0 + ty) * 40 + tx] = acc;
    }
}

// ---------------------------------------------------------------------------
// launch
// ---------------------------------------------------------------------------
extern "C" void kernel_launch(void* const* d_in, const int* in_sizes, int n_in,
                              void* d_out, int out_size) {
    const float* x_in    = (const float*)d_in[0];
    const int*   eidx    = (const int*)d_in[1];
    const float* fc1_w   = (const float*)d_in[2];
    const float* fc1_b   = (const float*)d_in[3];
    const float* conv_w  = (const float*)d_in[4];
    const float* bn_g    = (const float*)d_in[5];
    const float* bn_b    = (const float*)d_in[6];
    const float* fc2_w   = (const float*)d_in[7];
    const float* fc2_b   = (const float*)d_in[8];
    float* out = (float*)d_out;

    int N = in_sizes[0] / IN_DIM;
    int E = in_sizes[1] / 2;
    if (N > N_NODES) N = N_NODES;
    if (E > E_EDGES) E = E_EDGES;
    int NB = (N + 255) / 256;

    __half *p_xsh, *p_x0h;
    float *p_hp, *p_h2;
    cudaGetSymbolAddress((void**)&p_xsh, g_xsh);
    cudaGetSymbolAddress((void**)&p_x0h, g_x0h);
    cudaGetSymbolAddress((void**)&p_hp, g_hp);
    cudaGetSymbolAddress((void**)&p_h2, g_h2);

    // ---- graph preprocessing (CSR + dinv) ----
    detect_idx_kernel<<<1, 512>>>(eidx, 2 * E);
    zero_all_kernel<<<NB, 256>>>(N);
    count_edges_kernel<<<(E + 255) / 256, 256>>>(eidx, E);
    scan1_kernel<<<NB, 256>>>(N);
    scan2_kernel<<<1, SCAN_NB_MAX>>>(NB, N);
    scan3_kernel<<<NB, 256>>>(N);
    scatter_edges_kernel<<<(E + 255) / 256, 256>>>(eidx, E);

    int gemm_grid = (N + GBM - 1) / GBM;

    // ---- fc1 + relu: writes only fp16 x0h + xsh ----
    gemm_tf32_kernel<<<gemm_grid, 256>>>(
        x_in, fc1_w, fc1_b, nullptr, 0.f, 0.f, /*relu=*/1, /*write_half=*/1,
        /*stat_layer=*/-1, /*out=*/nullptr, N, IN_DIM);

    int gather_grid = (N * 32 + 255) / 256;
    int ew_grid = (N * 96 + 255) / 256;

    for (int i = 0; i < 3; i++) {
        float beta = logf(0.5f / (float)(i + 1) + 1.0f);
        gather_kernel<<<gather_grid, 256>>>(p_xsh, p_x0h, p_hp, N);
        gemm_tf32_kernel<<<gemm_grid, 256>>>(
            p_hp, conv_w + (size_t)i * H_DIM * H_DIM, nullptr, p_hp,
            1.f - beta, beta, /*relu=*/0, /*write_half=*/0, /*stat_layer=*/i,
            p_h2, N, H_DIM);
        if (i < 2) {
            bn_apply_kernel<<<ew_grid, 256>>>(
                p_h2, bn_g + i * H_DIM, bn_b + i * H_DIM, i, N);
        }
    }

    // ---- fc2 with layer-2 BN+ReLU fused ----
    fc2_kernel<<<512, 320>>>(p_h2, fc2_w, fc2_b, bn_g + 2 * H_DIM,
                             bn_b + 2 * H_DIM, 2, out, N);
}